// round 2
// baseline (speedup 1.0000x reference)
#include <cuda_runtime.h>
#include <cstdint>

// ---------------- problem constants ----------------
#define D_DIM 3072
#define N_DIM 8192
#define B_DIM 2

#define TM 128            // CTA M tile (d)
#define TN 128            // CTA N tile (n)
#define TK 32             // K tile (floats)
#define STAGES 4
#define NK (N_DIM / TK)   // 256 k iterations
#define MT (D_DIM / TM)   // 24
#define NT (N_DIM / TN)   // 64

#define ROWF 36                          // padded row length in floats (16B aligned, conflict-free)
#define TILE_F (128 * ROWF)              // floats per 128-row tile = 4608
#define STAGE_F (2 * TILE_F)             // A + B per stage = 9216 floats
#define SMEM_BYTES (STAGES * STAGE_F * 4)  // 147456

// ---------------- PTX helpers ----------------
__device__ __forceinline__ uint32_t smem_u32(const void* p) {
    uint32_t a;
    asm("{ .reg .u64 t; cvta.to.shared.u64 t, %1; cvt.u32.u64 %0, t; }" : "=r"(a) : "l"(p));
    return a;
}

__device__ __forceinline__ void cp_async16(uint32_t saddr, const void* gaddr) {
    asm volatile("cp.async.cg.shared.global [%0], [%1], 16;" :: "r"(saddr), "l"(gaddr) : "memory");
}
#define CP_COMMIT() asm volatile("cp.async.commit_group;" ::: "memory")
#define CP_WAIT(n)  asm volatile("cp.async.wait_group %0;" :: "n"(n) : "memory")

__device__ __forceinline__ uint32_t f2tf32(float v) {
    uint32_t u;
    asm("cvt.rna.tf32.f32 %0, %1;" : "=r"(u) : "f"(v));
    return u;
}

__device__ __forceinline__ void mma_tf32(float& c0, float& c1, float& c2, float& c3,
                                         uint32_t a0, uint32_t a1, uint32_t a2, uint32_t a3,
                                         uint32_t b0, uint32_t b1) {
    asm volatile(
        "mma.sync.aligned.m16n8k8.row.col.f32.tf32.tf32.f32 "
        "{%0,%1,%2,%3}, {%4,%5,%6,%7}, {%8,%9}, {%0,%1,%2,%3};"
        : "+f"(c0), "+f"(c1), "+f"(c2), "+f"(c3)
        : "r"(a0), "r"(a1), "r"(a2), "r"(a3), "r"(b0), "r"(b1));
}

// ---------------- kernel ----------------
__global__ void __launch_bounds__(256, 1)
gcn_tf32_mma_kernel(float* __restrict__ out,
                    const float* __restrict__ x,
                    const float* __restrict__ adj)
{
    extern __shared__ float smem[];
    const uint32_t sbase = smem_u32(smem);

    const int tid = threadIdx.x;
    const int wid = tid >> 5;
    const int lane = tid & 31;

    // M-fast rasterization: one 148-CTA wave covers all 24 m-tiles for ~6 n-tiles,
    // so adj tiles (the big operand) stay hot in L2 across the wave.
    const int bx = blockIdx.x;
    const int mt = bx % MT;
    const int nt = (bx / MT) % NT;
    const int b  = bx / (MT * NT);
    const int d0 = mt * TM;
    const int n0 = nt * TN;

    // warp tile: 64 (m) x 32 (n); warps: 2 in m, 4 in n
    const int wm = (wid & 1) * 64;
    const int wn = (wid >> 1) * 32;

    // ---- cp.async addressing: 256 threads, each copies 4 A-chunks + 4 B-chunks of 16B ----
    const int crow = tid >> 3;           // 0..31
    const int cc   = tid & 7;            // 16B chunk within 128B row
    const float* gA = x   + ((size_t)b * D_DIM + d0 + crow) * N_DIM + cc * 4;
    const float* gB = adj + ((size_t)b * N_DIM + n0 + crow) * N_DIM + cc * 4;
    const uint32_t sA_st = sbase + (uint32_t)(crow * ROWF + cc * 4) * 4;
    const uint32_t sB_st = sA_st + TILE_F * 4;

    // fragment addressing (conflict-free: bank = (4*row + col) mod 32)
    const int frow = lane >> 2;          // 0..7
    const int fcol = lane & 3;           // 0..3

    float acc[4][4][4];
    #pragma unroll
    for (int i = 0; i < 4; i++)
        #pragma unroll
        for (int j = 0; j < 4; j++)
            #pragma unroll
            for (int r = 0; r < 4; r++) acc[i][j][r] = 0.0f;

    // ---- prologue: fill STAGES-1 stages ----
    #pragma unroll
    for (int s = 0; s < STAGES - 1; s++) {
        const size_t k0 = (size_t)s * TK;
        #pragma unroll
        for (int i = 0; i < 4; i++) {
            cp_async16(sA_st + (uint32_t)(s * STAGE_F + i * 32 * ROWF) * 4, gA + k0 + (size_t)i * 32 * N_DIM);
            cp_async16(sB_st + (uint32_t)(s * STAGE_F + i * 32 * ROWF) * 4, gB + k0 + (size_t)i * 32 * N_DIM);
        }
        CP_COMMIT();
    }
    CP_WAIT(STAGES - 2);
    __syncthreads();

    // ---- main loop ----
    for (int k = 0; k < NK; k++) {
        const int cur = k & (STAGES - 1);

        // issue loads for stage k+3
        if (k + STAGES - 1 < NK) {
            const int s = (k + STAGES - 1) & (STAGES - 1);
            const size_t k0 = (size_t)(k + STAGES - 1) * TK;
            #pragma unroll
            for (int i = 0; i < 4; i++) {
                cp_async16(sA_st + (uint32_t)(s * STAGE_F + i * 32 * ROWF) * 4, gA + k0 + (size_t)i * 32 * N_DIM);
                cp_async16(sB_st + (uint32_t)(s * STAGE_F + i * 32 * ROWF) * 4, gB + k0 + (size_t)i * 32 * N_DIM);
            }
        }
        CP_COMMIT();

        // compute stage cur: 4 k-steps of 8
        const float* sA = smem + cur * STAGE_F;
        const float* sB = sA + TILE_F;
        #pragma unroll
        for (int kb = 0; kb < 4; kb++) {
            const int kk = kb * 8;
            uint32_t af[4][4];
            uint32_t bf[4][2];
            #pragma unroll
            for (int mi = 0; mi < 4; mi++) {
                const float* ap = sA + (wm + mi * 16 + frow) * ROWF + kk + fcol;
                af[mi][0] = f2tf32(ap[0]);
                af[mi][1] = f2tf32(ap[8 * ROWF]);
                af[mi][2] = f2tf32(ap[4]);
                af[mi][3] = f2tf32(ap[8 * ROWF + 4]);
            }
            #pragma unroll
            for (int ni = 0; ni < 4; ni++) {
                const float* bp = sB + (wn + ni * 8 + frow) * ROWF + kk + fcol;
                bf[ni][0] = f2tf32(bp[0]);
                bf[ni][1] = f2tf32(bp[4]);
            }
            #pragma unroll
            for (int mi = 0; mi < 4; mi++)
                #pragma unroll
                for (int ni = 0; ni < 4; ni++)
                    mma_tf32(acc[mi][ni][0], acc[mi][ni][1], acc[mi][ni][2], acc[mi][ni][3],
                             af[mi][0], af[mi][1], af[mi][2], af[mi][3],
                             bf[ni][0], bf[ni][1]);
        }

        CP_WAIT(STAGES - 2);
        __syncthreads();
    }

    // ---- epilogue: fp32 stores (float2 per c-pair) ----
    float* ob = out + ((size_t)b * D_DIM) * N_DIM;
    #pragma unroll
    for (int mi = 0; mi < 4; mi++) {
        const int r0 = d0 + wm + mi * 16 + (lane >> 2);
        #pragma unroll
        for (int ni = 0; ni < 4; ni++) {
            const int c = n0 + wn + ni * 8 + (lane & 3) * 2;
            float2 v0 = make_float2(acc[mi][ni][0], acc[mi][ni][1]);
            float2 v1 = make_float2(acc[mi][ni][2], acc[mi][ni][3]);
            *reinterpret_cast<float2*>(ob + (size_t)r0 * N_DIM + c) = v0;
            *reinterpret_cast<float2*>(ob + (size_t)(r0 + 8) * N_DIM + c) = v1;
        }
    }
}

// ---------------- host launch ----------------
extern "C" void kernel_launch(void* const* d_in, const int* in_sizes, int n_in,
                              void* d_out, int out_size)
{
    const float* x;
    const float* adj;
    if (in_sizes[0] == B_DIM * D_DIM * N_DIM) {
        x = (const float*)d_in[0]; adj = (const float*)d_in[1];
    } else {
        x = (const float*)d_in[1]; adj = (const float*)d_in[0];
    }

    static bool attr_set = false;
    // (setting an attribute is idempotent/deterministic; do it every call to stay stateless)
    cudaFuncSetAttribute(gcn_tf32_mma_kernel, cudaFuncAttributeMaxDynamicSharedMemorySize, SMEM_BYTES);
    (void)attr_set;

    gcn_tf32_mma_kernel<<<B_DIM * MT * NT, 256, SMEM_BYTES>>>((float*)d_out, x, adj);
}

// round 3
// speedup vs baseline: 1.9271x; 1.9271x over previous
#include <cuda_runtime.h>
#include <cuda_fp16.h>
#include <cstdint>

// ---------------- problem constants ----------------
#define D_DIM 3072
#define N_DIM 8192
#define B_DIM 2

#define TM 128            // CTA M tile (d)
#define TN 128            // CTA N tile (n)
#define TK 64             // K tile (halves) = 128B per row
#define STAGES 4
#define NK (N_DIM / TK)   // 128 k iterations
#define MT (D_DIM / TM)   // 24
#define NT (N_DIM / TN)   // 64

#define ROWH 72                           // padded row length in halves (conflict-free ldmatrix)
#define TILE_H (128 * ROWH)               // halves per 128-row tile = 9216
#define STAGE_H (2 * TILE_H)              // A + B per stage
#define SMEM_BYTES (STAGES * STAGE_H * 2) // 147456

// fp16 scratch copies of the inputs (zero-init .bss; no runtime allocation)
__device__ __half g_xh[(size_t)B_DIM * D_DIM * N_DIM];
__device__ __half g_adjh[(size_t)B_DIM * N_DIM * N_DIM];

// ---------------- PTX helpers ----------------
__device__ __forceinline__ uint32_t smem_u32(const void* p) {
    uint32_t a;
    asm("{ .reg .u64 t; cvta.to.shared.u64 t, %1; cvt.u32.u64 %0, t; }" : "=r"(a) : "l"(p));
    return a;
}
__device__ __forceinline__ void cp_async16(uint32_t saddr, const void* gaddr) {
    asm volatile("cp.async.cg.shared.global [%0], [%1], 16;" :: "r"(saddr), "l"(gaddr) : "memory");
}
#define CP_COMMIT() asm volatile("cp.async.commit_group;" ::: "memory")
#define CP_WAIT(n)  asm volatile("cp.async.wait_group %0;" :: "n"(n) : "memory")

__device__ __forceinline__ void ldmatrix_x4(uint32_t* r, uint32_t addr) {
    asm volatile("ldmatrix.sync.aligned.m8n8.x4.shared.b16 {%0,%1,%2,%3}, [%4];"
        : "=r"(r[0]), "=r"(r[1]), "=r"(r[2]), "=r"(r[3]) : "r"(addr));
}
__device__ __forceinline__ void ldmatrix_x2(uint32_t* r, uint32_t addr) {
    asm volatile("ldmatrix.sync.aligned.m8n8.x2.shared.b16 {%0,%1}, [%2];"
        : "=r"(r[0]), "=r"(r[1]) : "r"(addr));
}
__device__ __forceinline__ void mma_f16(float& c0, float& c1, float& c2, float& c3,
                                        uint32_t a0, uint32_t a1, uint32_t a2, uint32_t a3,
                                        uint32_t b0, uint32_t b1) {
    asm volatile(
        "mma.sync.aligned.m16n8k16.row.col.f32.f16.f16.f32 "
        "{%0,%1,%2,%3}, {%4,%5,%6,%7}, {%8,%9}, {%0,%1,%2,%3};"
        : "+f"(c0), "+f"(c1), "+f"(c2), "+f"(c3)
        : "r"(a0), "r"(a1), "r"(a2), "r"(a3), "r"(b0), "r"(b1));
}
__device__ __forceinline__ uint32_t pack_h2(float lo, float hi) {
    uint32_t u;
    asm("cvt.rn.f16x2.f32 %0, %1, %2;" : "=r"(u) : "f"(hi), "f"(lo));
    return u;
}

// ---------------- prepass: fp32 -> fp16 ----------------
__global__ void __launch_bounds__(256)
cvt_f2h_kernel(const float* __restrict__ src, __half* __restrict__ dst, size_t n)
{
    size_t i = ((size_t)blockIdx.x * blockDim.x + threadIdx.x) * 8;
    const size_t stride = (size_t)gridDim.x * blockDim.x * 8;
    for (; i < n; i += stride) {
        float4 f0 = *reinterpret_cast<const float4*>(src + i);
        float4 f1 = *reinterpret_cast<const float4*>(src + i + 4);
        uint4 v;
        v.x = pack_h2(f0.x, f0.y);
        v.y = pack_h2(f0.z, f0.w);
        v.z = pack_h2(f1.x, f1.y);
        v.w = pack_h2(f1.z, f1.w);
        *reinterpret_cast<uint4*>(dst + i) = v;
    }
}

// ---------------- main GEMM ----------------
__global__ void __launch_bounds__(256, 1)
gcn_f16_mma_kernel(float* __restrict__ out)
{
    extern __shared__ __half smem[];
    const uint32_t sbase = smem_u32(smem);

    const int tid = threadIdx.x;
    const int wid = tid >> 5;
    const int lane = tid & 31;

    // M-fast rasterization: a wave covers all 24 m-tiles for ~6 n-tiles -> adj hot in L2
    const int bx = blockIdx.x;
    const int mt = bx % MT;
    const int nt = (bx / MT) % NT;
    const int b  = bx / (MT * NT);
    const int d0 = mt * TM;
    const int n0 = nt * TN;

    // warp tile: 64 (m) x 32 (n); warps: 2 in m, 4 in n
    const int wm = (wid & 1) * 64;
    const int wn = (wid >> 1) * 32;

    // ---- cp.async addressing: 16B = 8 halves; tile = 128 rows x 8 chunks ----
    const int crow = tid >> 3;           // 0..31
    const int cc   = tid & 7;            // chunk within 128B row
    const __half* gA = g_xh   + ((size_t)b * D_DIM + d0 + crow) * N_DIM + cc * 8;
    const __half* gB = g_adjh + ((size_t)b * N_DIM + n0 + crow) * N_DIM + cc * 8;
    const uint32_t sA_st = sbase + (uint32_t)(crow * ROWH + cc * 8) * 2;
    const uint32_t sB_st = sA_st + TILE_H * 2;

    // ldmatrix per-lane row addresses (byte offsets within tile)
    // A x4: m-row = (lane&15), k-offset = (lane>>4)*8
    const uint32_t aOff = (uint32_t)(((wm + (lane & 15)) * ROWH + (lane >> 4) * 8) * 2);
    // B x2: n-row = (lane&7), k-offset = ((lane>>3)&1)*8
    const uint32_t bOff = (uint32_t)(((wn + (lane & 7)) * ROWH + ((lane >> 3) & 1) * 8) * 2) + TILE_H * 2;

    float acc[4][4][4];
    #pragma unroll
    for (int i = 0; i < 4; i++)
        #pragma unroll
        for (int j = 0; j < 4; j++)
            #pragma unroll
            for (int r = 0; r < 4; r++) acc[i][j][r] = 0.0f;

    // ---- prologue ----
    #pragma unroll
    for (int s = 0; s < STAGES - 1; s++) {
        const size_t k0 = (size_t)s * TK;
        #pragma unroll
        for (int i = 0; i < 4; i++) {
            cp_async16(sA_st + (uint32_t)(s * STAGE_H + i * 32 * ROWH) * 2, gA + k0 + (size_t)i * 32 * N_DIM);
            cp_async16(sB_st + (uint32_t)(s * STAGE_H + i * 32 * ROWH) * 2, gB + k0 + (size_t)i * 32 * N_DIM);
        }
        CP_COMMIT();
    }
    CP_WAIT(STAGES - 2);
    __syncthreads();

    // ---- main loop ----
    for (int k = 0; k < NK; k++) {
        const int cur = k & (STAGES - 1);

        if (k + STAGES - 1 < NK) {
            const int s = (k + STAGES - 1) & (STAGES - 1);
            const size_t k0 = (size_t)(k + STAGES - 1) * TK;
            #pragma unroll
            for (int i = 0; i < 4; i++) {
                cp_async16(sA_st + (uint32_t)(s * STAGE_H + i * 32 * ROWH) * 2, gA + k0 + (size_t)i * 32 * N_DIM);
                cp_async16(sB_st + (uint32_t)(s * STAGE_H + i * 32 * ROWH) * 2, gB + k0 + (size_t)i * 32 * N_DIM);
            }
        }
        CP_COMMIT();

        const uint32_t aBase = sbase + (uint32_t)(cur * STAGE_H) * 2 + aOff;
        const uint32_t bBase = sbase + (uint32_t)(cur * STAGE_H) * 2 + bOff;

        #pragma unroll
        for (int kb = 0; kb < 4; kb++) {        // 4 x k16 steps cover TK=64
            const uint32_t kByte = (uint32_t)(kb * 16 * 2);
            uint32_t af[4][4];
            uint32_t bf[4][2];
            #pragma unroll
            for (int mi = 0; mi < 4; mi++)
                ldmatrix_x4(af[mi], aBase + (uint32_t)(mi * 16 * ROWH * 2) + kByte);
            #pragma unroll
            for (int ni = 0; ni < 4; ni++)
                ldmatrix_x2(bf[ni], bBase + (uint32_t)(ni * 8 * ROWH * 2) + kByte);
            #pragma unroll
            for (int mi = 0; mi < 4; mi++)
                #pragma unroll
                for (int ni = 0; ni < 4; ni++)
                    mma_f16(acc[mi][ni][0], acc[mi][ni][1], acc[mi][ni][2], acc[mi][ni][3],
                            af[mi][0], af[mi][1], af[mi][2], af[mi][3],
                            bf[ni][0], bf[ni][1]);
        }

        CP_WAIT(STAGES - 2);
        __syncthreads();
    }

    // ---- epilogue: fp32 stores ----
    float* ob = out + ((size_t)b * D_DIM) * N_DIM;
    #pragma unroll
    for (int mi = 0; mi < 4; mi++) {
        const int r0 = d0 + wm + mi * 16 + (lane >> 2);
        #pragma unroll
        for (int ni = 0; ni < 4; ni++) {
            const int c = n0 + wn + ni * 8 + (lane & 3) * 2;
            float2 v0 = make_float2(acc[mi][ni][0], acc[mi][ni][1]);
            float2 v1 = make_float2(acc[mi][ni][2], acc[mi][ni][3]);
            *reinterpret_cast<float2*>(ob + (size_t)r0 * N_DIM + c) = v0;
            *reinterpret_cast<float2*>(ob + (size_t)(r0 + 8) * N_DIM + c) = v1;
        }
    }
}

// ---------------- host launch ----------------
extern "C" void kernel_launch(void* const* d_in, const int* in_sizes, int n_in,
                              void* d_out, int out_size)
{
    const float* x;
    const float* adj;
    if (in_sizes[0] == B_DIM * D_DIM * N_DIM) {
        x = (const float*)d_in[0]; adj = (const float*)d_in[1];
    } else {
        x = (const float*)d_in[1]; adj = (const float*)d_in[0];
    }

    __half* xh;
    __half* adjh;
    cudaGetSymbolAddress((void**)&xh, g_xh);
    cudaGetSymbolAddress((void**)&adjh, g_adjh);

    const size_t nx = (size_t)B_DIM * D_DIM * N_DIM;
    const size_t na = (size_t)B_DIM * N_DIM * N_DIM;
    cvt_f2h_kernel<<<2048, 256>>>(x, xh, nx);
    cvt_f2h_kernel<<<4096, 256>>>(adj, adjh, na);

    cudaFuncSetAttribute(gcn_f16_mma_kernel, cudaFuncAttributeMaxDynamicSharedMemorySize, SMEM_BYTES);
    gcn_f16_mma_kernel<<<B_DIM * MT * NT, 256, SMEM_BYTES>>>((float*)d_out);
}

// round 4
// speedup vs baseline: 2.0726x; 1.0754x over previous
#include <cuda_runtime.h>
#include <cuda_fp16.h>
#include <cstdint>

// ---------------- problem constants ----------------
#define D_DIM 3072
#define N_DIM 8192
#define B_DIM 2

#define TM 256            // CTA M tile (d)
#define TN 128            // CTA N tile (n)
#define TK 64             // K tile (halves) = 128B per row
#define STAGES 3
#define NK (N_DIM / TK)   // 128 k iterations
#define MT (D_DIM / TM)   // 12
#define NT (N_DIM / TN)   // 64

#define ROWH 72                           // padded row (halves): conflict-free ldmatrix
#define TILE_A_H (TM * ROWH)              // 18432 halves
#define TILE_B_H (TN * ROWH)              // 9216 halves
#define STAGE_H (TILE_A_H + TILE_B_H)     // 27648 halves = 55296 B
#define SMEM_BYTES (STAGES * STAGE_H * 2) // 165888

// fp16 scratch copies of the inputs (zero-init .bss; no runtime allocation)
__device__ __half g_xh[(size_t)B_DIM * D_DIM * N_DIM];
__device__ __half g_adjh[(size_t)B_DIM * N_DIM * N_DIM];

// ---------------- PTX helpers ----------------
__device__ __forceinline__ uint32_t smem_u32(const void* p) {
    uint32_t a;
    asm("{ .reg .u64 t; cvta.to.shared.u64 t, %1; cvt.u32.u64 %0, t; }" : "=r"(a) : "l"(p));
    return a;
}
__device__ __forceinline__ void cp_async16(uint32_t saddr, const void* gaddr) {
    asm volatile("cp.async.cg.shared.global [%0], [%1], 16;" :: "r"(saddr), "l"(gaddr) : "memory");
}
#define CP_COMMIT() asm volatile("cp.async.commit_group;" ::: "memory")
#define CP_WAIT(n)  asm volatile("cp.async.wait_group %0;" :: "n"(n) : "memory")

__device__ __forceinline__ void ldmatrix_x4(uint32_t* r, uint32_t addr) {
    asm volatile("ldmatrix.sync.aligned.m8n8.x4.shared.b16 {%0,%1,%2,%3}, [%4];"
        : "=r"(r[0]), "=r"(r[1]), "=r"(r[2]), "=r"(r[3]) : "r"(addr));
}
__device__ __forceinline__ void mma_f16(float& c0, float& c1, float& c2, float& c3,
                                        uint32_t a0, uint32_t a1, uint32_t a2, uint32_t a3,
                                        uint32_t b0, uint32_t b1) {
    asm volatile(
        "mma.sync.aligned.m16n8k16.row.col.f32.f16.f16.f32 "
        "{%0,%1,%2,%3}, {%4,%5,%6,%7}, {%8,%9}, {%0,%1,%2,%3};"
        : "+f"(c0), "+f"(c1), "+f"(c2), "+f"(c3)
        : "r"(a0), "r"(a1), "r"(a2), "r"(a3), "r"(b0), "r"(b1));
}
__device__ __forceinline__ uint32_t pack_h2(float lo, float hi) {
    uint32_t u;
    asm("cvt.rn.f16x2.f32 %0, %1, %2;" : "=r"(u) : "f"(hi), "f"(lo));
    return u;
}

// ---------------- prepass: fp32 -> fp16 ----------------
__global__ void __launch_bounds__(256)
cvt_f2h_kernel(const float* __restrict__ src, __half* __restrict__ dst, size_t n)
{
    size_t i = ((size_t)blockIdx.x * blockDim.x + threadIdx.x) * 8;
    const size_t stride = (size_t)gridDim.x * blockDim.x * 8;
    for (; i < n; i += stride) {
        float4 f0 = *reinterpret_cast<const float4*>(src + i);
        float4 f1 = *reinterpret_cast<const float4*>(src + i + 4);
        uint4 v;
        v.x = pack_h2(f0.x, f0.y);
        v.y = pack_h2(f0.z, f0.w);
        v.z = pack_h2(f1.x, f1.y);
        v.w = pack_h2(f1.z, f1.w);
        *reinterpret_cast<uint4*>(dst + i) = v;
    }
}

// ---------------- main GEMM: CTA 256x128, warp 64x64, 8 warps ----------------
__global__ void __launch_bounds__(256, 1)
gcn_f16_mma_kernel(float* __restrict__ out)
{
    extern __shared__ __half smem[];
    const uint32_t sbase = smem_u32(smem);

    const int tid = threadIdx.x;
    const int wid = tid >> 5;
    const int lane = tid & 31;

    // M-fast rasterization: a 152-CTA wave covers all 12 m-tiles for ~12 n-tiles,
    // so both adj rows and the whole x stay hot in L2 across the wave.
    const int bx = blockIdx.x;
    const int mt = bx % MT;
    const int nt = (bx / MT) % NT;
    const int b  = bx / (MT * NT);
    const int d0 = mt * TM;
    const int n0 = nt * TN;

    // warps: 4 in m, 2 in n; warp tile 64 (m) x 64 (n)
    const int wm = (wid & 3) * 64;
    const int wn = (wid >> 2) * 64;

    // ---- cp.async addressing: 16B chunks; A: 256 rows x 8 chunks (8/thread), B: 128 rows (4/thread)
    const int crow = tid >> 3;           // 0..31
    const int cc   = tid & 7;            // chunk within 128B row
    const __half* gA = g_xh   + ((size_t)b * D_DIM + d0 + crow) * N_DIM + cc * 8;
    const __half* gB = g_adjh + ((size_t)b * N_DIM + n0 + crow) * N_DIM + cc * 8;
    const uint32_t sA_st = sbase + (uint32_t)(crow * ROWH + cc * 8) * 2;
    const uint32_t sB_st = sA_st + TILE_A_H * 2;

    // ldmatrix lane addressing (byte offsets within stage):
    // A x4 (one m16k16 tile): row = wm + (lane&15), koff = (lane>>4)*8
    const uint32_t aOff = (uint32_t)(((wm + (lane & 15)) * ROWH + (lane >> 4) * 8) * 2);
    // B x4 (two n8k16 tiles): row = wn + ((lane>>4)<<3) + (lane&7), koff = ((lane>>3)&1)*8
    const uint32_t bOff = (uint32_t)(((wn + ((lane >> 4) << 3) + (lane & 7)) * ROWH
                                      + ((lane >> 3) & 1) * 8) * 2) + TILE_A_H * 2;

    float acc[4][8][4];
    #pragma unroll
    for (int i = 0; i < 4; i++)
        #pragma unroll
        for (int j = 0; j < 8; j++)
            #pragma unroll
            for (int r = 0; r < 4; r++) acc[i][j][r] = 0.0f;

    // ---- prologue ----
    #pragma unroll
    for (int s = 0; s < STAGES - 1; s++) {
        const size_t k0 = (size_t)s * TK;
        #pragma unroll
        for (int i = 0; i < 8; i++)
            cp_async16(sA_st + (uint32_t)(s * STAGE_H + i * 32 * ROWH) * 2, gA + k0 + (size_t)i * 32 * N_DIM);
        #pragma unroll
        for (int i = 0; i < 4; i++)
            cp_async16(sB_st + (uint32_t)(s * STAGE_H + i * 32 * ROWH) * 2, gB + k0 + (size_t)i * 32 * N_DIM);
        CP_COMMIT();
    }
    CP_WAIT(STAGES - 2);
    __syncthreads();

    // ---- main loop ----
    for (int k = 0; k < NK; k++) {
        const int cur = k % STAGES;

        if (k + STAGES - 1 < NK) {
            const int s = (k + STAGES - 1) % STAGES;
            const size_t k0 = (size_t)(k + STAGES - 1) * TK;
            #pragma unroll
            for (int i = 0; i < 8; i++)
                cp_async16(sA_st + (uint32_t)(s * STAGE_H + i * 32 * ROWH) * 2, gA + k0 + (size_t)i * 32 * N_DIM);
            #pragma unroll
            for (int i = 0; i < 4; i++)
                cp_async16(sB_st + (uint32_t)(s * STAGE_H + i * 32 * ROWH) * 2, gB + k0 + (size_t)i * 32 * N_DIM);
        }
        CP_COMMIT();

        const uint32_t aBase = sbase + (uint32_t)(cur * STAGE_H) * 2 + aOff;
        const uint32_t bBase = sbase + (uint32_t)(cur * STAGE_H) * 2 + bOff;

        #pragma unroll
        for (int kb = 0; kb < 4; kb++) {        // 4 x k16 steps cover TK=64
            const uint32_t kByte = (uint32_t)(kb * 16 * 2);
            uint32_t af[4][4];
            uint32_t bf[4][4];                  // bf[p] covers n-tiles 2p, 2p+1
            #pragma unroll
            for (int mi = 0; mi < 4; mi++)
                ldmatrix_x4(af[mi], aBase + (uint32_t)(mi * 16 * ROWH * 2) + kByte);
            #pragma unroll
            for (int np = 0; np < 4; np++)
                ldmatrix_x4(bf[np], bBase + (uint32_t)(np * 16 * ROWH * 2) + kByte);
            #pragma unroll
            for (int mi = 0; mi < 4; mi++)
                #pragma unroll
                for (int np = 0; np < 4; np++) {
                    mma_f16(acc[mi][2*np][0], acc[mi][2*np][1], acc[mi][2*np][2], acc[mi][2*np][3],
                            af[mi][0], af[mi][1], af[mi][2], af[mi][3],
                            bf[np][0], bf[np][1]);
                    mma_f16(acc[mi][2*np+1][0], acc[mi][2*np+1][1], acc[mi][2*np+1][2], acc[mi][2*np+1][3],
                            af[mi][0], af[mi][1], af[mi][2], af[mi][3],
                            bf[np][2], bf[np][3]);
                }
        }

        CP_WAIT(STAGES - 2);
        __syncthreads();
    }

    // ---- epilogue: fp32 stores ----
    float* ob = out + ((size_t)b * D_DIM) * N_DIM;
    #pragma unroll
    for (int mi = 0; mi < 4; mi++) {
        const int r0 = d0 + wm + mi * 16 + (lane >> 2);
        #pragma unroll
        for (int ni = 0; ni < 8; ni++) {
            const int c = n0 + wn + ni * 8 + (lane & 3) * 2;
            float2 v0 = make_float2(acc[mi][ni][0], acc[mi][ni][1]);
            float2 v1 = make_float2(acc[mi][ni][2], acc[mi][ni][3]);
            *reinterpret_cast<float2*>(ob + (size_t)r0 * N_DIM + c) = v0;
            *reinterpret_cast<float2*>(ob + (size_t)(r0 + 8) * N_DIM + c) = v1;
        }
    }
}

// ---------------- host launch ----------------
extern "C" void kernel_launch(void* const* d_in, const int* in_sizes, int n_in,
                              void* d_out, int out_size)
{
    const float* x;
    const float* adj;
    if (in_sizes[0] == B_DIM * D_DIM * N_DIM) {
        x = (const float*)d_in[0]; adj = (const float*)d_in[1];
    } else {
        x = (const float*)d_in[1]; adj = (const float*)d_in[0];
    }

    __half* xh;
    __half* adjh;
    cudaGetSymbolAddress((void**)&xh, g_xh);
    cudaGetSymbolAddress((void**)&adjh, g_adjh);

    const size_t nx = (size_t)B_DIM * D_DIM * N_DIM;
    const size_t na = (size_t)B_DIM * N_DIM * N_DIM;
    cvt_f2h_kernel<<<2048, 256>>>(x, xh, nx);
    cvt_f2h_kernel<<<4096, 256>>>(adj, adjh, na);

    cudaFuncSetAttribute(gcn_f16_mma_kernel, cudaFuncAttributeMaxDynamicSharedMemorySize, SMEM_BYTES);
    gcn_f16_mma_kernel<<<B_DIM * MT * NT, 256, SMEM_BYTES>>>((float*)d_out);
}

// round 5
// speedup vs baseline: 2.4434x; 1.1789x over previous
#include <cuda_runtime.h>
#include <cuda_fp16.h>
#include <cstdint>

// ---------------- problem constants ----------------
#define D_DIM 3072
#define N_DIM 8192
#define B_DIM 2

#define TM 128            // CTA M tile (d)
#define TN 128            // CTA N tile (n)
#define TK 64             // K tile (halves) = 128B per row
#define STAGES 3
#define NK (N_DIM / TK)   // 128 k iterations
#define MT (D_DIM / TM)   // 24
#define NT (N_DIM / TN)   // 64

#define ROWH 72                           // padded row (halves): conflict-free ldmatrix
#define TILE_H (128 * ROWH)               // 9216 halves per 128-row tile
#define STAGE_H (2 * TILE_H)              // A + B per stage = 18432 halves = 36864 B
#define SMEM_BYTES (STAGES * STAGE_H * 2) // 110592 B -> 2 CTAs/SM

// fp16 scratch copies of the inputs (zero-init .bss; no runtime allocation)
__device__ __half g_xh[(size_t)B_DIM * D_DIM * N_DIM];
__device__ __half g_adjh[(size_t)B_DIM * N_DIM * N_DIM];

// ---------------- PTX helpers ----------------
__device__ __forceinline__ uint32_t smem_u32(const void* p) {
    uint32_t a;
    asm("{ .reg .u64 t; cvta.to.shared.u64 t, %1; cvt.u32.u64 %0, t; }" : "=r"(a) : "l"(p));
    return a;
}
__device__ __forceinline__ void cp_async16(uint32_t saddr, const void* gaddr) {
    asm volatile("cp.async.cg.shared.global [%0], [%1], 16;" :: "r"(saddr), "l"(gaddr) : "memory");
}
#define CP_COMMIT() asm volatile("cp.async.commit_group;" ::: "memory")
#define CP_WAIT(n)  asm volatile("cp.async.wait_group %0;" :: "n"(n) : "memory")

__device__ __forceinline__ void ldmatrix_x4(uint32_t* r, uint32_t addr) {
    asm volatile("ldmatrix.sync.aligned.m8n8.x4.shared.b16 {%0,%1,%2,%3}, [%4];"
        : "=r"(r[0]), "=r"(r[1]), "=r"(r[2]), "=r"(r[3]) : "r"(addr));
}
__device__ __forceinline__ void mma_f16(float& c0, float& c1, float& c2, float& c3,
                                        uint32_t a0, uint32_t a1, uint32_t a2, uint32_t a3,
                                        uint32_t b0, uint32_t b1) {
    asm volatile(
        "mma.sync.aligned.m16n8k16.row.col.f32.f16.f16.f32 "
        "{%0,%1,%2,%3}, {%4,%5,%6,%7}, {%8,%9}, {%0,%1,%2,%3};"
        : "+f"(c0), "+f"(c1), "+f"(c2), "+f"(c3)
        : "r"(a0), "r"(a1), "r"(a2), "r"(a3), "r"(b0), "r"(b1));
}
__device__ __forceinline__ uint32_t pack_h2(float lo, float hi) {
    uint32_t u;
    asm("cvt.rn.f16x2.f32 %0, %1, %2;" : "=r"(u) : "f"(hi), "f"(lo));
    return u;
}

// ---------------- prepass: fp32 -> fp16 ----------------
__global__ void __launch_bounds__(256)
cvt_f2h_kernel(const float* __restrict__ src, __half* __restrict__ dst, size_t n)
{
    size_t i = ((size_t)blockIdx.x * blockDim.x + threadIdx.x) * 8;
    const size_t stride = (size_t)gridDim.x * blockDim.x * 8;
    for (; i < n; i += stride) {
        float4 f0 = *reinterpret_cast<const float4*>(src + i);
        float4 f1 = *reinterpret_cast<const float4*>(src + i + 4);
        uint4 v;
        v.x = pack_h2(f0.x, f0.y);
        v.y = pack_h2(f0.z, f0.w);
        v.z = pack_h2(f1.x, f1.y);
        v.w = pack_h2(f1.z, f1.w);
        *reinterpret_cast<uint4*>(dst + i) = v;
    }
}

// ---------------- main GEMM: CTA 128x128, 4 warps (64x64 each), 2 CTAs/SM ----------------
__global__ void __launch_bounds__(128, 2)
gcn_f16_mma_kernel(float* __restrict__ out)
{
    extern __shared__ __half smem[];
    const uint32_t sbase = smem_u32(smem);

    const int tid = threadIdx.x;
    const int wid = tid >> 5;      // 0..3
    const int lane = tid & 31;

    // M-fast rasterization: a 304-CTA wave covers all 24 m-tiles for ~13 n-tiles,
    // so x tiles (48MB) + adj tiles (26MB) stay hot in L2 across the wave.
    const int bx = blockIdx.x;
    const int mt = bx % MT;
    const int nt = (bx / MT) % NT;
    const int b  = bx / (MT * NT);
    const int d0 = mt * TM;
    const int n0 = nt * TN;

    // warps: 2 in m, 2 in n; warp tile 64 (m) x 64 (n)
    const int wm = (wid & 1) * 64;
    const int wn = (wid >> 1) * 64;

    // ---- cp.async addressing: 16B chunks; A/B each 128 rows x 8 chunks, 8 chunks/thread each
    const int crow = tid >> 3;           // 0..15
    const int cc   = tid & 7;            // chunk within 128B row
    const __half* gA = g_xh   + ((size_t)b * D_DIM + d0 + crow) * N_DIM + cc * 8;
    const __half* gB = g_adjh + ((size_t)b * N_DIM + n0 + crow) * N_DIM + cc * 8;
    const uint32_t sA_st = sbase + (uint32_t)(crow * ROWH + cc * 8) * 2;
    const uint32_t sB_st = sA_st + TILE_H * 2;

    // ldmatrix lane addressing (byte offsets within stage):
    // A x4 (one m16k16 tile): row = wm + (lane&15), koff = (lane>>4)*8
    const uint32_t aOff = (uint32_t)(((wm + (lane & 15)) * ROWH + (lane >> 4) * 8) * 2);
    // B x4 (two n8k16 tiles): row = wn + ((lane>>4)<<3) + (lane&7), koff = ((lane>>3)&1)*8
    const uint32_t bOff = (uint32_t)(((wn + ((lane >> 4) << 3) + (lane & 7)) * ROWH
                                      + ((lane >> 3) & 1) * 8) * 2) + TILE_H * 2;

    float acc[4][8][4];
    #pragma unroll
    for (int i = 0; i < 4; i++)
        #pragma unroll
        for (int j = 0; j < 8; j++)
            #pragma unroll
            for (int r = 0; r < 4; r++) acc[i][j][r] = 0.0f;

    // ---- prologue ----
    #pragma unroll
    for (int s = 0; s < STAGES - 1; s++) {
        const size_t k0 = (size_t)s * TK;
        #pragma unroll
        for (int i = 0; i < 8; i++) {
            cp_async16(sA_st + (uint32_t)(s * STAGE_H + i * 16 * ROWH) * 2, gA + k0 + (size_t)i * 16 * N_DIM);
            cp_async16(sB_st + (uint32_t)(s * STAGE_H + i * 16 * ROWH) * 2, gB + k0 + (size_t)i * 16 * N_DIM);
        }
        CP_COMMIT();
    }
    CP_WAIT(STAGES - 2);
    __syncthreads();

    // ---- main loop ----
    for (int k = 0; k < NK; k++) {
        const int cur = k % STAGES;

        if (k + STAGES - 1 < NK) {
            const int s = (k + STAGES - 1) % STAGES;
            const size_t k0 = (size_t)(k + STAGES - 1) * TK;
            #pragma unroll
            for (int i = 0; i < 8; i++) {
                cp_async16(sA_st + (uint32_t)(s * STAGE_H + i * 16 * ROWH) * 2, gA + k0 + (size_t)i * 16 * N_DIM);
                cp_async16(sB_st + (uint32_t)(s * STAGE_H + i * 16 * ROWH) * 2, gB + k0 + (size_t)i * 16 * N_DIM);
            }
        }
        CP_COMMIT();

        const uint32_t aBase = sbase + (uint32_t)(cur * STAGE_H) * 2 + aOff;
        const uint32_t bBase = sbase + (uint32_t)(cur * STAGE_H) * 2 + bOff;

        #pragma unroll
        for (int kb = 0; kb < 4; kb++) {        // 4 x k16 steps cover TK=64
            const uint32_t kByte = (uint32_t)(kb * 16 * 2);
            uint32_t af[4][4];
            uint32_t bf[4][4];                  // bf[p] covers n-tiles 2p, 2p+1
            #pragma unroll
            for (int mi = 0; mi < 4; mi++)
                ldmatrix_x4(af[mi], aBase + (uint32_t)(mi * 16 * ROWH * 2) + kByte);
            #pragma unroll
            for (int np = 0; np < 4; np++)
                ldmatrix_x4(bf[np], bBase + (uint32_t)(np * 16 * ROWH * 2) + kByte);
            #pragma unroll
            for (int mi = 0; mi < 4; mi++)
                #pragma unroll
                for (int np = 0; np < 4; np++) {
                    mma_f16(acc[mi][2*np][0], acc[mi][2*np][1], acc[mi][2*np][2], acc[mi][2*np][3],
                            af[mi][0], af[mi][1], af[mi][2], af[mi][3],
                            bf[np][0], bf[np][1]);
                    mma_f16(acc[mi][2*np+1][0], acc[mi][2*np+1][1], acc[mi][2*np+1][2], acc[mi][2*np+1][3],
                            af[mi][0], af[mi][1], af[mi][2], af[mi][3],
                            bf[np][2], bf[np][3]);
                }
        }

        CP_WAIT(STAGES - 2);
        __syncthreads();
    }

    // ---- epilogue: fp32 stores ----
    float* ob = out + ((size_t)b * D_DIM) * N_DIM;
    #pragma unroll
    for (int mi = 0; mi < 4; mi++) {
        const int r0 = d0 + wm + mi * 16 + (lane >> 2);
        #pragma unroll
        for (int ni = 0; ni < 8; ni++) {
            const int c = n0 + wn + ni * 8 + (lane & 3) * 2;
            float2 v0 = make_float2(acc[mi][ni][0], acc[mi][ni][1]);
            float2 v1 = make_float2(acc[mi][ni][2], acc[mi][ni][3]);
            *reinterpret_cast<float2*>(ob + (size_t)r0 * N_DIM + c) = v0;
            *reinterpret_cast<float2*>(ob + (size_t)(r0 + 8) * N_DIM + c) = v1;
        }
    }
}

// ---------------- host launch ----------------
extern "C" void kernel_launch(void* const* d_in, const int* in_sizes, int n_in,
                              void* d_out, int out_size)
{
    const float* x;
    const float* adj;
    if (in_sizes[0] == B_DIM * D_DIM * N_DIM) {
        x = (const float*)d_in[0]; adj = (const float*)d_in[1];
    } else {
        x = (const float*)d_in[1]; adj = (const float*)d_in[0];
    }

    __half* xh;
    __half* adjh;
    cudaGetSymbolAddress((void**)&xh, g_xh);
    cudaGetSymbolAddress((void**)&adjh, g_adjh);

    const size_t nx = (size_t)B_DIM * D_DIM * N_DIM;
    const size_t na = (size_t)B_DIM * N_DIM * N_DIM;
    cvt_f2h_kernel<<<2048, 256>>>(x, xh, nx);
    cvt_f2h_kernel<<<4096, 256>>>(adj, adjh, na);

    cudaFuncSetAttribute(gcn_f16_mma_kernel, cudaFuncAttributeMaxDynamicSharedMemorySize, SMEM_BYTES);
    gcn_f16_mma_kernel<<<B_DIM * MT * NT, 128, SMEM_BYTES>>>((float*)d_out);
}

// round 6
// speedup vs baseline: 3.0229x; 1.2372x over previous
#include <cuda_runtime.h>
#include <cuda_fp16.h>
#include <cstdint>

// ---------------- problem constants ----------------
#define D_DIM 3072
#define N_DIM 8192
#define B_DIM 2

#define TM 128            // CTA M tile (d)
#define TN 128            // CTA N tile (n)
#define TK 64             // K tile (halves) = 128B per row
#define STAGES 3
#define NK (N_DIM / TK)   // 128 k iterations
#define MT (D_DIM / TM)   // 24
#define NT (N_DIM / TN)   // 64

#define ROWH 72                           // padded row (halves): conflict-free ldmatrix
#define TILE_H (128 * ROWH)               // 9216 halves per 128-row tile
#define STAGE_H (2 * TILE_H)              // A + B per stage = 18432 halves = 36864 B
#define SMEM_BYTES (STAGES * STAGE_H * 2) // 110592 B -> 2 CTAs/SM

// fp16 scratch copies of the inputs (zero-init .bss; no runtime allocation)
__device__ __half g_xh[(size_t)B_DIM * D_DIM * N_DIM];
__device__ __half g_adjh[(size_t)B_DIM * N_DIM * N_DIM];

// ---------------- PTX helpers ----------------
__device__ __forceinline__ uint32_t smem_u32(const void* p) {
    uint32_t a;
    asm("{ .reg .u64 t; cvta.to.shared.u64 t, %1; cvt.u32.u64 %0, t; }" : "=r"(a) : "l"(p));
    return a;
}
__device__ __forceinline__ void cp_async16(uint32_t saddr, const void* gaddr) {
    asm volatile("cp.async.cg.shared.global [%0], [%1], 16;" :: "r"(saddr), "l"(gaddr) : "memory");
}
#define CP_COMMIT() asm volatile("cp.async.commit_group;" ::: "memory")
#define CP_WAIT(n)  asm volatile("cp.async.wait_group %0;" :: "n"(n) : "memory")

__device__ __forceinline__ void ldmatrix_x4(uint32_t* r, uint32_t addr) {
    asm volatile("ldmatrix.sync.aligned.m8n8.x4.shared.b16 {%0,%1,%2,%3}, [%4];"
        : "=r"(r[0]), "=r"(r[1]), "=r"(r[2]), "=r"(r[3]) : "r"(addr));
}
__device__ __forceinline__ void mma_f16(float& c0, float& c1, float& c2, float& c3,
                                        uint32_t a0, uint32_t a1, uint32_t a2, uint32_t a3,
                                        uint32_t b0, uint32_t b1) {
    asm volatile(
        "mma.sync.aligned.m16n8k16.row.col.f32.f16.f16.f32 "
        "{%0,%1,%2,%3}, {%4,%5,%6,%7}, {%8,%9}, {%0,%1,%2,%3};"
        : "+f"(c0), "+f"(c1), "+f"(c2), "+f"(c3)
        : "r"(a0), "r"(a1), "r"(a2), "r"(a3), "r"(b0), "r"(b1));
}
__device__ __forceinline__ uint32_t pack_h2(float lo, float hi) {
    uint32_t u;
    asm("cvt.rn.f16x2.f32 %0, %1, %2;" : "=r"(u) : "f"(hi), "f"(lo));
    return u;
}

// ---------------- prepass: fp32 -> fp16 ----------------
__global__ void __launch_bounds__(256)
cvt_f2h_kernel(const float* __restrict__ src, __half* __restrict__ dst, size_t n)
{
    size_t i = ((size_t)blockIdx.x * blockDim.x + threadIdx.x) * 8;
    const size_t stride = (size_t)gridDim.x * blockDim.x * 8;
    for (; i < n; i += stride) {
        float4 f0 = *reinterpret_cast<const float4*>(src + i);
        float4 f1 = *reinterpret_cast<const float4*>(src + i + 4);
        uint4 v;
        v.x = pack_h2(f0.x, f0.y);
        v.y = pack_h2(f0.z, f0.w);
        v.z = pack_h2(f1.x, f1.y);
        v.w = pack_h2(f1.z, f1.w);
        *reinterpret_cast<uint4*>(dst + i) = v;
    }
}

// ---------------- main GEMM: CTA 128x128, 4 warps (64x64 each), 2 CTAs/SM ----------------
__global__ void __launch_bounds__(128, 2)
gcn_f16_mma_kernel(float* __restrict__ out)
{
    extern __shared__ __half smem[];
    const uint32_t sbase = smem_u32(smem);

    const int tid = threadIdx.x;
    const int wid = tid >> 5;      // 0..3
    const int lane = tid & 31;

    // M-fast rasterization: a 304-CTA wave covers all 24 m-tiles for ~13 n-tiles,
    // so x tiles + adj tiles stay hot in L2 across the wave.
    const int bx = blockIdx.x;
    const int mt = bx % MT;
    const int nt = (bx / MT) % NT;
    const int b  = bx / (MT * NT);
    const int d0 = mt * TM;
    const int n0 = nt * TN;

    // warps: 2 in m, 2 in n; warp tile 64 (m) x 64 (n)
    const int wm = (wid & 1) * 64;
    const int wn = (wid >> 1) * 64;

    // ---- cp.async addressing: 16B chunks; A/B each 128 rows x 8 chunks, 8 chunks/thread each
    const int crow = tid >> 3;           // 0..15
    const int cc   = tid & 7;            // chunk within 128B row
    const __half* gA = g_xh   + ((size_t)b * D_DIM + d0 + crow) * N_DIM + cc * 8;
    const __half* gB = g_adjh + ((size_t)b * N_DIM + n0 + crow) * N_DIM + cc * 8;
    const uint32_t sA_st = sbase + (uint32_t)(crow * ROWH + cc * 8) * 2;
    const uint32_t sB_st = sA_st + TILE_H * 2;

    // ldmatrix lane addressing (byte offsets within stage):
    // A x4 (one m16k16 tile): row = wm + (lane&15), koff = (lane>>4)*8
    const uint32_t aOff = (uint32_t)(((wm + (lane & 15)) * ROWH + (lane >> 4) * 8) * 2);
    // B x4 (two n8k16 tiles): row = wn + ((lane>>4)<<3) + (lane&7), koff = ((lane>>3)&1)*8
    const uint32_t bOff = (uint32_t)(((wn + ((lane >> 4) << 3) + (lane & 7)) * ROWH
                                      + ((lane >> 3) & 1) * 8) * 2) + TILE_H * 2;

    float acc[4][8][4];
    #pragma unroll
    for (int i = 0; i < 4; i++)
        #pragma unroll
        for (int j = 0; j < 8; j++)
            #pragma unroll
            for (int r = 0; r < 4; r++) acc[i][j][r] = 0.0f;

    // ---- prologue ----
    #pragma unroll
    for (int s = 0; s < STAGES - 1; s++) {
        const size_t k0 = (size_t)s * TK;
        #pragma unroll
        for (int i = 0; i < 8; i++) {
            cp_async16(sA_st + (uint32_t)(s * STAGE_H + i * 16 * ROWH) * 2, gA + k0 + (size_t)i * 16 * N_DIM);
            cp_async16(sB_st + (uint32_t)(s * STAGE_H + i * 16 * ROWH) * 2, gB + k0 + (size_t)i * 16 * N_DIM);
        }
        CP_COMMIT();
    }
    CP_WAIT(STAGES - 2);
    __syncthreads();

    // fragment double buffers (software pipeline across kb steps)
    uint32_t af[2][4][4];
    uint32_t bf[2][4][4];

    // preload kb=0 of stage 0
    {
        const uint32_t aBase = sbase + aOff;
        const uint32_t bBase = sbase + bOff;
        #pragma unroll
        for (int mi = 0; mi < 4; mi++)
            ldmatrix_x4(af[0][mi], aBase + (uint32_t)(mi * 16 * ROWH * 2));
        #pragma unroll
        for (int np = 0; np < 4; np++)
            ldmatrix_x4(bf[0][np], bBase + (uint32_t)(np * 16 * ROWH * 2));
    }

    // ---- main loop ----
    for (int k = 0; k < NK; k++) {
        const int cur = k % STAGES;

        if (k + STAGES - 1 < NK) {
            const int s = (k + STAGES - 1) % STAGES;
            const size_t k0 = (size_t)(k + STAGES - 1) * TK;
            #pragma unroll
            for (int i = 0; i < 8; i++) {
                cp_async16(sA_st + (uint32_t)(s * STAGE_H + i * 16 * ROWH) * 2, gA + k0 + (size_t)i * 16 * N_DIM);
                cp_async16(sB_st + (uint32_t)(s * STAGE_H + i * 16 * ROWH) * 2, gB + k0 + (size_t)i * 16 * N_DIM);
            }
        }
        CP_COMMIT();

        const uint32_t aBase = sbase + (uint32_t)(cur * STAGE_H) * 2 + aOff;
        const uint32_t bBase = sbase + (uint32_t)(cur * STAGE_H) * 2 + bOff;

        #pragma unroll
        for (int kb = 0; kb < 4; kb++) {        // 4 x k16 steps cover TK=64
            const int cb = kb & 1;
            const int nb = cb ^ 1;

            // prefetch next kb's fragments (from same stage) before this kb's MMAs
            if (kb < 3) {
                const uint32_t kByte = (uint32_t)((kb + 1) * 16 * 2);
                #pragma unroll
                for (int mi = 0; mi < 4; mi++)
                    ldmatrix_x4(af[nb][mi], aBase + (uint32_t)(mi * 16 * ROWH * 2) + kByte);
                #pragma unroll
                for (int np = 0; np < 4; np++)
                    ldmatrix_x4(bf[nb][np], bBase + (uint32_t)(np * 16 * ROWH * 2) + kByte);
            }

            #pragma unroll
            for (int mi = 0; mi < 4; mi++)
                #pragma unroll
                for (int np = 0; np < 4; np++) {
                    mma_f16(acc[mi][2*np][0], acc[mi][2*np][1], acc[mi][2*np][2], acc[mi][2*np][3],
                            af[cb][mi][0], af[cb][mi][1], af[cb][mi][2], af[cb][mi][3],
                            bf[cb][np][0], bf[cb][np][1]);
                    mma_f16(acc[mi][2*np+1][0], acc[mi][2*np+1][1], acc[mi][2*np+1][2], acc[mi][2*np+1][3],
                            af[cb][mi][0], af[cb][mi][1], af[cb][mi][2], af[cb][mi][3],
                            bf[cb][np][2], bf[cb][np][3]);
                }
        }

        CP_WAIT(STAGES - 2);
        __syncthreads();

        // preload kb=0 of the next stage (data guaranteed resident after the wait+sync)
        if (k + 1 < NK) {
            const int nxt = (k + 1) % STAGES;
            const uint32_t aB2 = sbase + (uint32_t)(nxt * STAGE_H) * 2 + aOff;
            const uint32_t bB2 = sbase + (uint32_t)(nxt * STAGE_H) * 2 + bOff;
            #pragma unroll
            for (int mi = 0; mi < 4; mi++)
                ldmatrix_x4(af[0][mi], aB2 + (uint32_t)(mi * 16 * ROWH * 2));
            #pragma unroll
            for (int np = 0; np < 4; np++)
                ldmatrix_x4(bf[0][np], bB2 + (uint32_t)(np * 16 * ROWH * 2));
        }
    }

    // ---- epilogue: fp32 stores ----
    float* ob = out + ((size_t)b * D_DIM) * N_DIM;
    #pragma unroll
    for (int mi = 0; mi < 4; mi++) {
        const int r0 = d0 + wm + mi * 16 + (lane >> 2);
        #pragma unroll
        for (int ni = 0; ni < 8; ni++) {
            const int c = n0 + wn + ni * 8 + (lane & 3) * 2;
            float2 v0 = make_float2(acc[mi][ni][0], acc[mi][ni][1]);
            float2 v1 = make_float2(acc[mi][ni][2], acc[mi][ni][3]);
            *reinterpret_cast<float2*>(ob + (size_t)r0 * N_DIM + c) = v0;
            *reinterpret_cast<float2*>(ob + (size_t)(r0 + 8) * N_DIM + c) = v1;
        }
    }
}

// ---------------- host launch ----------------
extern "C" void kernel_launch(void* const* d_in, const int* in_sizes, int n_in,
                              void* d_out, int out_size)
{
    const float* x;
    const float* adj;
    if (in_sizes[0] == B_DIM * D_DIM * N_DIM) {
        x = (const float*)d_in[0]; adj = (const float*)d_in[1];
    } else {
        x = (const float*)d_in[1]; adj = (const float*)d_in[0];
    }

    __half* xh;
    __half* adjh;
    cudaGetSymbolAddress((void**)&xh, g_xh);
    cudaGetSymbolAddress((void**)&adjh, g_adjh);

    const size_t nx = (size_t)B_DIM * D_DIM * N_DIM;
    const size_t na = (size_t)B_DIM * N_DIM * N_DIM;
    cvt_f2h_kernel<<<2048, 256>>>(x, xh, nx);
    cvt_f2h_kernel<<<4096, 256>>>(adj, adjh, na);

    cudaFuncSetAttribute(gcn_f16_mma_kernel, cudaFuncAttributeMaxDynamicSharedMemorySize, SMEM_BYTES);
    gcn_f16_mma_kernel<<<B_DIM * MT * NT, 128, SMEM_BYTES>>>((float*)d_out);
}

// round 7
// speedup vs baseline: 3.2089x; 1.0615x over previous
#include <cuda_runtime.h>
#include <cuda_fp16.h>
#include <cstdint>

// ---------------- problem constants ----------------
#define D_DIM 3072
#define N_DIM 8192
#define B_DIM 2

#define TM 128            // CTA M tile (d)
#define TN 128            // CTA N tile (n)
#define TK 64             // K tile (halves) = 128B per row
#define STAGES 3
#define NK (N_DIM / TK)   // 128 k iterations
#define MT (D_DIM / TM)   // 24
#define NT (N_DIM / TN)   // 64

#define ROWH 72                           // padded row (halves): conflict-free ldmatrix
#define TILE_H (128 * ROWH)               // 9216 halves per 128-row tile
#define STAGE_H (2 * TILE_H)              // A + B per stage = 18432 halves = 36864 B
#define SMEM_BYTES (STAGES * STAGE_H * 2) // 110592 B -> 2 CTAs/SM

// fp16 scratch copies of the inputs (zero-init .bss; no runtime allocation)
__device__ __half g_xh[(size_t)B_DIM * D_DIM * N_DIM];
__device__ __half g_adjh[(size_t)B_DIM * N_DIM * N_DIM];

// ---------------- PTX helpers ----------------
__device__ __forceinline__ uint32_t smem_u32(const void* p) {
    uint32_t a;
    asm("{ .reg .u64 t; cvta.to.shared.u64 t, %1; cvt.u32.u64 %0, t; }" : "=r"(a) : "l"(p));
    return a;
}
__device__ __forceinline__ void cp_async16(uint32_t saddr, const void* gaddr) {
    asm volatile("cp.async.cg.shared.global [%0], [%1], 16;" :: "r"(saddr), "l"(gaddr) : "memory");
}
#define CP_COMMIT() asm volatile("cp.async.commit_group;" ::: "memory")
#define CP_WAIT(n)  asm volatile("cp.async.wait_group %0;" :: "n"(n) : "memory")

__device__ __forceinline__ void ldmatrix_x4(uint32_t* r, uint32_t addr) {
    asm volatile("ldmatrix.sync.aligned.m8n8.x4.shared.b16 {%0,%1,%2,%3}, [%4];"
        : "=r"(r[0]), "=r"(r[1]), "=r"(r[2]), "=r"(r[3]) : "r"(addr));
}
__device__ __forceinline__ void mma_f16(float& c0, float& c1, float& c2, float& c3,
                                        uint32_t a0, uint32_t a1, uint32_t a2, uint32_t a3,
                                        uint32_t b0, uint32_t b1) {
    asm volatile(
        "mma.sync.aligned.m16n8k16.row.col.f32.f16.f16.f32 "
        "{%0,%1,%2,%3}, {%4,%5,%6,%7}, {%8,%9}, {%0,%1,%2,%3};"
        : "+f"(c0), "+f"(c1), "+f"(c2), "+f"(c3)
        : "r"(a0), "r"(a1), "r"(a2), "r"(a3), "r"(b0), "r"(b1));
}
__device__ __forceinline__ uint32_t pack_h2(float lo, float hi) {
    uint32_t u;
    asm("cvt.rn.f16x2.f32 %0, %1, %2;" : "=r"(u) : "f"(hi), "f"(lo));
    return u;
}

// ---------------- prepass: fp32 -> fp16 ----------------
__global__ void __launch_bounds__(256)
cvt_f2h_kernel(const float* __restrict__ src, __half* __restrict__ dst, size_t n)
{
    size_t i = ((size_t)blockIdx.x * blockDim.x + threadIdx.x) * 8;
    const size_t stride = (size_t)gridDim.x * blockDim.x * 8;
    for (; i < n; i += stride) {
        float4 f0 = *reinterpret_cast<const float4*>(src + i);
        float4 f1 = *reinterpret_cast<const float4*>(src + i + 4);
        uint4 v;
        v.x = pack_h2(f0.x, f0.y);
        v.y = pack_h2(f0.z, f0.w);
        v.z = pack_h2(f1.x, f1.y);
        v.w = pack_h2(f1.z, f1.w);
        *reinterpret_cast<uint4*>(dst + i) = v;
    }
}

// ---------------- main GEMM: CTA 128x128, 4 warps (64x64 each), 2 CTAs/SM ----------------
__global__ void __launch_bounds__(128, 2)
gcn_f16_mma_kernel(float* __restrict__ out)
{
    extern __shared__ __half smem[];
    const uint32_t sbase = smem_u32(smem);

    const int tid = threadIdx.x;
    const int wid = tid >> 5;      // 0..3
    const int lane = tid & 31;

    // M-fast rasterization keeps x + adj tiles hot in L2 across a wave.
    const int bx = blockIdx.x;
    const int mt = bx % MT;
    const int nt = (bx / MT) % NT;
    const int b  = bx / (MT * NT);
    const int d0 = mt * TM;
    const int n0 = nt * TN;

    // warps: 2 in m, 2 in n; warp tile 64 (m) x 64 (n)
    const int wm = (wid & 1) * 64;
    const int wn = (wid >> 1) * 64;

    // ---- cp.async addressing: 16B chunks; A/B each 128 rows x 8 chunks, 8 chunks/thread each
    const int crow = tid >> 3;           // 0..15
    const int cc   = tid & 7;            // chunk within 128B row
    const __half* gA = g_xh   + ((size_t)b * D_DIM + d0 + crow) * N_DIM + cc * 8;
    const __half* gB = g_adjh + ((size_t)b * N_DIM + n0 + crow) * N_DIM + cc * 8;
    const uint32_t sA_st = sbase + (uint32_t)(crow * ROWH + cc * 8) * 2;
    const uint32_t sB_st = sA_st + TILE_H * 2;

    // ldmatrix lane addressing (byte offsets within stage):
    const uint32_t aOff = (uint32_t)(((wm + (lane & 15)) * ROWH + (lane >> 4) * 8) * 2);
    const uint32_t bOff = (uint32_t)(((wn + ((lane >> 4) << 3) + (lane & 7)) * ROWH
                                      + ((lane >> 3) & 1) * 8) * 2) + TILE_H * 2;

    float acc[4][8][4];
    #pragma unroll
    for (int i = 0; i < 4; i++)
        #pragma unroll
        for (int j = 0; j < 8; j++)
            #pragma unroll
            for (int r = 0; r < 4; r++) acc[i][j][r] = 0.0f;

    // ---- prologue ----
    #pragma unroll
    for (int s = 0; s < STAGES - 1; s++) {
        const size_t k0 = (size_t)s * TK;
        #pragma unroll
        for (int i = 0; i < 8; i++) {
            cp_async16(sA_st + (uint32_t)(s * STAGE_H + i * 16 * ROWH) * 2, gA + k0 + (size_t)i * 16 * N_DIM);
            cp_async16(sB_st + (uint32_t)(s * STAGE_H + i * 16 * ROWH) * 2, gB + k0 + (size_t)i * 16 * N_DIM);
        }
        CP_COMMIT();
    }
    CP_WAIT(STAGES - 2);
    __syncthreads();

    // fragment double buffers (software pipeline across kb steps)
    uint32_t af[2][4][4];
    uint32_t bf[2][4][4];

    // preload kb=0 of stage 0
    {
        const uint32_t aBase = sbase + aOff;
        const uint32_t bBase = sbase + bOff;
        #pragma unroll
        for (int mi = 0; mi < 4; mi++)
            ldmatrix_x4(af[0][mi], aBase + (uint32_t)(mi * 16 * ROWH * 2));
        #pragma unroll
        for (int np = 0; np < 4; np++)
            ldmatrix_x4(bf[0][np], bBase + (uint32_t)(np * 16 * ROWH * 2));
    }

    // ---- main loop ----
    for (int k = 0; k < NK; k++) {
        const int cur = k % STAGES;
        const bool do_pref = (k + STAGES - 1 < NK);
        const int s = (k + STAGES - 1) % STAGES;
        const size_t k0 = (size_t)(k + STAGES - 1) * TK;

        const uint32_t aBase = sbase + (uint32_t)(cur * STAGE_H) * 2 + aOff;
        const uint32_t bBase = sbase + (uint32_t)(cur * STAGE_H) * 2 + bOff;

        #pragma unroll
        for (int kb = 0; kb < 4; kb++) {        // 4 x k16 steps cover TK=64
            const int cb = kb & 1;
            const int nb = cb ^ 1;

            // prefetch next kb's fragments (from same stage) before this kb's MMAs
            if (kb < 3) {
                const uint32_t kByte = (uint32_t)((kb + 1) * 16 * 2);
                #pragma unroll
                for (int mi = 0; mi < 4; mi++)
                    ldmatrix_x4(af[nb][mi], aBase + (uint32_t)(mi * 16 * ROWH * 2) + kByte);
                #pragma unroll
                for (int np = 0; np < 4; np++)
                    ldmatrix_x4(bf[nb][np], bBase + (uint32_t)(np * 16 * ROWH * 2) + kByte);
            }

            #pragma unroll
            for (int mi = 0; mi < 4; mi++)
                #pragma unroll
                for (int np = 0; np < 4; np++) {
                    mma_f16(acc[mi][2*np][0], acc[mi][2*np][1], acc[mi][2*np][2], acc[mi][2*np][3],
                            af[cb][mi][0], af[cb][mi][1], af[cb][mi][2], af[cb][mi][3],
                            bf[cb][np][0], bf[cb][np][1]);
                    mma_f16(acc[mi][2*np+1][0], acc[mi][2*np+1][1], acc[mi][2*np+1][2], acc[mi][2*np+1][3],
                            af[cb][mi][0], af[cb][mi][1], af[cb][mi][2], af[cb][mi][3],
                            bf[cb][np][2], bf[cb][np][3]);
                }

            // spread the next-stage cp.asyncs across kb steps, AFTER this kb's MMAs:
            // kb0 -> A rows 0-63, kb1 -> A rows 64-127, kb2 -> B rows 0-63, kb3 -> B rows 64-127
            if (do_pref) {
                #pragma unroll
                for (int i = 0; i < 4; i++) {
                    const int r = (kb & 1) * 4 + i;
                    if (kb < 2)
                        cp_async16(sA_st + (uint32_t)(s * STAGE_H + r * 16 * ROWH) * 2,
                                   gA + k0 + (size_t)r * 16 * N_DIM);
                    else
                        cp_async16(sB_st + (uint32_t)(s * STAGE_H + r * 16 * ROWH) * 2,
                                   gB + k0 + (size_t)r * 16 * N_DIM);
                }
            }
        }
        CP_COMMIT();

        CP_WAIT(STAGES - 2);
        __syncthreads();

        // preload kb=0 of the next stage (data guaranteed resident after the wait+sync)
        if (k + 1 < NK) {
            const int nxt = (k + 1) % STAGES;
            const uint32_t aB2 = sbase + (uint32_t)(nxt * STAGE_H) * 2 + aOff;
            const uint32_t bB2 = sbase + (uint32_t)(nxt * STAGE_H) * 2 + bOff;
            #pragma unroll
            for (int mi = 0; mi < 4; mi++)
                ldmatrix_x4(af[0][mi], aB2 + (uint32_t)(mi * 16 * ROWH * 2));
            #pragma unroll
            for (int np = 0; np < 4; np++)
                ldmatrix_x4(bf[0][np], bB2 + (uint32_t)(np * 16 * ROWH * 2));
        }
    }

    // ---- epilogue: fp32 stores ----
    float* ob = out + ((size_t)b * D_DIM) * N_DIM;
    #pragma unroll
    for (int mi = 0; mi < 4; mi++) {
        const int r0 = d0 + wm + mi * 16 + (lane >> 2);
        #pragma unroll
        for (int ni = 0; ni < 8; ni++) {
            const int c = n0 + wn + ni * 8 + (lane & 3) * 2;
            float2 v0 = make_float2(acc[mi][ni][0], acc[mi][ni][1]);
            float2 v1 = make_float2(acc[mi][ni][2], acc[mi][ni][3]);
            *reinterpret_cast<float2*>(ob + (size_t)r0 * N_DIM + c) = v0;
            *reinterpret_cast<float2*>(ob + (size_t)(r0 + 8) * N_DIM + c) = v1;
        }
    }
}

// ---------------- host launch ----------------
extern "C" void kernel_launch(void* const* d_in, const int* in_sizes, int n_in,
                              void* d_out, int out_size)
{
    const float* x;
    const float* adj;
    if (in_sizes[0] == B_DIM * D_DIM * N_DIM) {
        x = (const float*)d_in[0]; adj = (const float*)d_in[1];
    } else {
        x = (const float*)d_in[1]; adj = (const float*)d_in[0];
    }

    __half* xh;
    __half* adjh;
    cudaGetSymbolAddress((void**)&xh, g_xh);
    cudaGetSymbolAddress((void**)&adjh, g_adjh);

    const size_t nx = (size_t)B_DIM * D_DIM * N_DIM;
    const size_t na = (size_t)B_DIM * N_DIM * N_DIM;
    cvt_f2h_kernel<<<2048, 256>>>(x, xh, nx);
    cvt_f2h_kernel<<<4096, 256>>>(adj, adjh, na);

    cudaFuncSetAttribute(gcn_f16_mma_kernel, cudaFuncAttributeMaxDynamicSharedMemorySize, SMEM_BYTES);
    gcn_f16_mma_kernel<<<B_DIM * MT * NT, 128, SMEM_BYTES>>>((float*)d_out);
}

// round 8
// speedup vs baseline: 3.2887x; 1.0249x over previous
#include <cuda_runtime.h>
#include <cuda_fp16.h>
#include <cstdint>

// ---------------- problem constants ----------------
#define D_DIM 3072
#define N_DIM 8192
#define B_DIM 2

#define TM 128            // CTA M tile (d)
#define TN 128            // CTA N tile (n)
#define TK 64             // K tile (halves) = 128B per row
#define STAGES 3
#define NK (N_DIM / TK)   // 128 k iterations
#define MT (D_DIM / TM)   // 24
#define NT (N_DIM / TN)   // 64

#define TOTAL_TILES (B_DIM * MT * NT)  // 3072
#define MAIN_TILES  3040               // 304 slots x 10 waves exactly
#define REM_TILES   (TOTAL_TILES - MAIN_TILES)  // 32
#define KSPLIT      8
#define NK_PART     (NK / KSPLIT)      // 16

#define ROWH 72                           // padded row (halves): conflict-free ldmatrix
#define TILE_H (128 * ROWH)               // 9216 halves per 128-row tile
#define STAGE_H (2 * TILE_H)              // A + B per stage = 36864 B
#define SMEM_BYTES (STAGES * STAGE_H * 2) // 110592 B -> 2 CTAs/SM

// fp16 scratch copies of the inputs (zero-init .bss; no runtime allocation)
__device__ __half g_xh[(size_t)B_DIM * D_DIM * N_DIM];
__device__ __half g_adjh[(size_t)B_DIM * N_DIM * N_DIM];
// split-K partials for the 32 remainder tiles: [32*8][128*128]
__device__ float g_part[(size_t)REM_TILES * KSPLIT * TM * TN];

// ---------------- PTX helpers ----------------
__device__ __forceinline__ uint32_t smem_u32(const void* p) {
    uint32_t a;
    asm("{ .reg .u64 t; cvta.to.shared.u64 t, %1; cvt.u32.u64 %0, t; }" : "=r"(a) : "l"(p));
    return a;
}
__device__ __forceinline__ void cp_async16(uint32_t saddr, const void* gaddr) {
    asm volatile("cp.async.cg.shared.global [%0], [%1], 16;" :: "r"(saddr), "l"(gaddr) : "memory");
}
#define CP_COMMIT() asm volatile("cp.async.commit_group;" ::: "memory")
#define CP_WAIT(n)  asm volatile("cp.async.wait_group %0;" :: "n"(n) : "memory")

__device__ __forceinline__ void ldmatrix_x4(uint32_t* r, uint32_t addr) {
    asm volatile("ldmatrix.sync.aligned.m8n8.x4.shared.b16 {%0,%1,%2,%3}, [%4];"
        : "=r"(r[0]), "=r"(r[1]), "=r"(r[2]), "=r"(r[3]) : "r"(addr));
}
__device__ __forceinline__ void mma_f16(float& c0, float& c1, float& c2, float& c3,
                                        uint32_t a0, uint32_t a1, uint32_t a2, uint32_t a3,
                                        uint32_t b0, uint32_t b1) {
    asm volatile(
        "mma.sync.aligned.m16n8k16.row.col.f32.f16.f16.f32 "
        "{%0,%1,%2,%3}, {%4,%5,%6,%7}, {%8,%9}, {%0,%1,%2,%3};"
        : "+f"(c0), "+f"(c1), "+f"(c2), "+f"(c3)
        : "r"(a0), "r"(a1), "r"(a2), "r"(a3), "r"(b0), "r"(b1));
}
__device__ __forceinline__ uint32_t pack_h2(float lo, float hi) {
    uint32_t u;
    asm("cvt.rn.f16x2.f32 %0, %1, %2;" : "=r"(u) : "f"(hi), "f"(lo));
    return u;
}

// ---------------- prepass: fp32 -> fp16 ----------------
__global__ void __launch_bounds__(256)
cvt_f2h_kernel(const float* __restrict__ src, __half* __restrict__ dst, size_t n)
{
    size_t i = ((size_t)blockIdx.x * blockDim.x + threadIdx.x) * 8;
    const size_t stride = (size_t)gridDim.x * blockDim.x * 8;
    for (; i < n; i += stride) {
        float4 f0 = *reinterpret_cast<const float4*>(src + i);
        float4 f1 = *reinterpret_cast<const float4*>(src + i + 4);
        uint4 v;
        v.x = pack_h2(f0.x, f0.y);
        v.y = pack_h2(f0.z, f0.w);
        v.z = pack_h2(f1.x, f1.y);
        v.w = pack_h2(f1.z, f1.w);
        *reinterpret_cast<uint4*>(dst + i) = v;
    }
}

// ---------------- shared GEMM body ----------------
// Computes acc for tile (b, d0, n0) over k iterations [kbeg, kend).
struct GemmCtx {
    uint32_t sA_st, sB_st, aOff, bOff, sbase;
    const __half* gA;
    const __half* gB;
};

__device__ __forceinline__ void gemm_tile(const GemmCtx& cx, int kbeg, int kend,
                                          float acc[4][8][4])
{
    const uint32_t sbase = cx.sbase;
    // prologue
    #pragma unroll
    for (int s = 0; s < STAGES - 1; s++) {
        const size_t k0 = (size_t)(kbeg + s) * TK;
        #pragma unroll
        for (int i = 0; i < 8; i++) {
            cp_async16(cx.sA_st + (uint32_t)(s * STAGE_H + i * 16 * ROWH) * 2, cx.gA + k0 + (size_t)i * 16 * N_DIM);
            cp_async16(cx.sB_st + (uint32_t)(s * STAGE_H + i * 16 * ROWH) * 2, cx.gB + k0 + (size_t)i * 16 * N_DIM);
        }
        CP_COMMIT();
    }
    CP_WAIT(STAGES - 2);
    __syncthreads();

    uint32_t af[2][4][4];
    uint32_t bf[2][4][4];

    // preload kb=0 of first stage
    {
        const uint32_t aBase = sbase + cx.aOff;
        const uint32_t bBase = sbase + cx.bOff;
        #pragma unroll
        for (int mi = 0; mi < 4; mi++)
            ldmatrix_x4(af[0][mi], aBase + (uint32_t)(mi * 16 * ROWH * 2));
        #pragma unroll
        for (int np = 0; np < 4; np++)
            ldmatrix_x4(bf[0][np], bBase + (uint32_t)(np * 16 * ROWH * 2));
    }

    for (int k = kbeg; k < kend; k++) {
        const int cur = (k - kbeg) % STAGES;
        const bool do_pref = (k + STAGES - 1 < kend);
        const int s = (k - kbeg + STAGES - 1) % STAGES;
        const size_t k0 = (size_t)(k + STAGES - 1) * TK;

        const uint32_t aBase = sbase + (uint32_t)(cur * STAGE_H) * 2 + cx.aOff;
        const uint32_t bBase = sbase + (uint32_t)(cur * STAGE_H) * 2 + cx.bOff;

        #pragma unroll
        for (int kb = 0; kb < 4; kb++) {
            const int cb = kb & 1;
            const int nb = cb ^ 1;

            if (kb < 3) {
                const uint32_t kByte = (uint32_t)((kb + 1) * 16 * 2);
                #pragma unroll
                for (int mi = 0; mi < 4; mi++)
                    ldmatrix_x4(af[nb][mi], aBase + (uint32_t)(mi * 16 * ROWH * 2) + kByte);
                #pragma unroll
                for (int np = 0; np < 4; np++)
                    ldmatrix_x4(bf[nb][np], bBase + (uint32_t)(np * 16 * ROWH * 2) + kByte);
            }

            #pragma unroll
            for (int mi = 0; mi < 4; mi++)
                #pragma unroll
                for (int np = 0; np < 4; np++) {
                    mma_f16(acc[mi][2*np][0], acc[mi][2*np][1], acc[mi][2*np][2], acc[mi][2*np][3],
                            af[cb][mi][0], af[cb][mi][1], af[cb][mi][2], af[cb][mi][3],
                            bf[cb][np][0], bf[cb][np][1]);
                    mma_f16(acc[mi][2*np+1][0], acc[mi][2*np+1][1], acc[mi][2*np+1][2], acc[mi][2*np+1][3],
                            af[cb][mi][0], af[cb][mi][1], af[cb][mi][2], af[cb][mi][3],
                            bf[cb][np][2], bf[cb][np][3]);
                }

            // spread next-stage cp.asyncs across kb steps, after this kb's MMAs
            if (do_pref) {
                #pragma unroll
                for (int i = 0; i < 4; i++) {
                    const int r = (kb & 1) * 4 + i;
                    if (kb < 2)
                        cp_async16(cx.sA_st + (uint32_t)(s * STAGE_H + r * 16 * ROWH) * 2,
                                   cx.gA + k0 + (size_t)r * 16 * N_DIM);
                    else
                        cp_async16(cx.sB_st + (uint32_t)(s * STAGE_H + r * 16 * ROWH) * 2,
                                   cx.gB + k0 + (size_t)r * 16 * N_DIM);
                }
            }
        }
        CP_COMMIT();

        CP_WAIT(STAGES - 2);
        __syncthreads();

        if (k + 1 < kend) {
            const int nxt = (k + 1 - kbeg) % STAGES;
            const uint32_t aB2 = sbase + (uint32_t)(nxt * STAGE_H) * 2 + cx.aOff;
            const uint32_t bB2 = sbase + (uint32_t)(nxt * STAGE_H) * 2 + cx.bOff;
            #pragma unroll
            for (int mi = 0; mi < 4; mi++)
                ldmatrix_x4(af[0][mi], aB2 + (uint32_t)(mi * 16 * ROWH * 2));
            #pragma unroll
            for (int np = 0; np < 4; np++)
                ldmatrix_x4(bf[0][np], bB2 + (uint32_t)(np * 16 * ROWH * 2));
        }
    }
}

__device__ __forceinline__ void make_ctx(GemmCtx& cx, uint32_t sbase, int tid,
                                         int b, int d0, int n0, int wm, int wn)
{
    const int lane = tid & 31;
    const int crow = tid >> 3;
    const int cc   = tid & 7;
    cx.sbase = sbase;
    cx.gA = g_xh   + ((size_t)b * D_DIM + d0 + crow) * N_DIM + cc * 8;
    cx.gB = g_adjh + ((size_t)b * N_DIM + n0 + crow) * N_DIM + cc * 8;
    cx.sA_st = sbase + (uint32_t)(crow * ROWH + cc * 8) * 2;
    cx.sB_st = cx.sA_st + TILE_H * 2;
    cx.aOff = (uint32_t)(((wm + (lane & 15)) * ROWH + (lane >> 4) * 8) * 2);
    cx.bOff = (uint32_t)(((wn + ((lane >> 4) << 3) + (lane & 7)) * ROWH
                          + ((lane >> 3) & 1) * 8) * 2) + TILE_H * 2;
}

// ---------------- kernel 1: main tiles (exactly 10 full waves) ----------------
__global__ void __launch_bounds__(128, 2)
gcn_f16_mma_kernel(float* __restrict__ out)
{
    extern __shared__ __half smem[];
    const uint32_t sbase = smem_u32(smem);
    const int tid = threadIdx.x;
    const int wid = tid >> 5;
    const int lane = tid & 31;

    const int bx = blockIdx.x;
    const int mt = bx % MT;
    const int nt = (bx / MT) % NT;
    const int b  = bx / (MT * NT);
    const int d0 = mt * TM;
    const int n0 = nt * TN;
    const int wm = (wid & 1) * 64;
    const int wn = (wid >> 1) * 64;

    GemmCtx cx;
    make_ctx(cx, sbase, tid, b, d0, n0, wm, wn);

    float acc[4][8][4];
    #pragma unroll
    for (int i = 0; i < 4; i++)
        #pragma unroll
        for (int j = 0; j < 8; j++)
            #pragma unroll
            for (int r = 0; r < 4; r++) acc[i][j][r] = 0.0f;

    gemm_tile(cx, 0, NK, acc);

    float* ob = out + ((size_t)b * D_DIM) * N_DIM;
    #pragma unroll
    for (int mi = 0; mi < 4; mi++) {
        const int r0 = d0 + wm + mi * 16 + (lane >> 2);
        #pragma unroll
        for (int ni = 0; ni < 8; ni++) {
            const int c = n0 + wn + ni * 8 + (lane & 3) * 2;
            float2 v0 = make_float2(acc[mi][ni][0], acc[mi][ni][1]);
            float2 v1 = make_float2(acc[mi][ni][2], acc[mi][ni][3]);
            *reinterpret_cast<float2*>(ob + (size_t)r0 * N_DIM + c) = v0;
            *reinterpret_cast<float2*>(ob + (size_t)(r0 + 8) * N_DIM + c) = v1;
        }
    }
}

// ---------------- kernel 2: remainder tiles with split-K=8, partials to scratch ----------------
__global__ void __launch_bounds__(128, 2)
gcn_f16_mma_rem_kernel()
{
    extern __shared__ __half smem[];
    const uint32_t sbase = smem_u32(smem);
    const int tid = threadIdx.x;
    const int wid = tid >> 5;
    const int lane = tid & 31;

    const int bx = blockIdx.x;                 // 0..255
    const int tile = MAIN_TILES + (bx >> 3);   // 3040..3071
    const int kp = bx & 7;

    const int mt = tile % MT;
    const int nt = (tile / MT) % NT;
    const int b  = tile / (MT * NT);
    const int d0 = mt * TM;
    const int n0 = nt * TN;
    const int wm = (wid & 1) * 64;
    const int wn = (wid >> 1) * 64;

    GemmCtx cx;
    make_ctx(cx, sbase, tid, b, d0, n0, wm, wn);

    float acc[4][8][4];
    #pragma unroll
    for (int i = 0; i < 4; i++)
        #pragma unroll
        for (int j = 0; j < 8; j++)
            #pragma unroll
            for (int r = 0; r < 4; r++) acc[i][j][r] = 0.0f;

    gemm_tile(cx, kp * NK_PART, (kp + 1) * NK_PART, acc);

    // store partials row-major [128][128] into g_part[bx]
    float* pb = g_part + (size_t)bx * (TM * TN);
    #pragma unroll
    for (int mi = 0; mi < 4; mi++) {
        const int r0 = wm + mi * 16 + (lane >> 2);
        #pragma unroll
        for (int ni = 0; ni < 8; ni++) {
            const int c = wn + ni * 8 + (lane & 3) * 2;
            float2 v0 = make_float2(acc[mi][ni][0], acc[mi][ni][1]);
            float2 v1 = make_float2(acc[mi][ni][2], acc[mi][ni][3]);
            *reinterpret_cast<float2*>(pb + (size_t)r0 * TN + c) = v0;
            *reinterpret_cast<float2*>(pb + (size_t)(r0 + 8) * TN + c) = v1;
        }
    }
}

// ---------------- kernel 3: reduce 8 partials per remainder tile into out ----------------
__global__ void __launch_bounds__(256)
reduce_rem_kernel(float* __restrict__ out)
{
    // 32 tiles x 16384 elems / 4 per thread = 131072 threads -> 512 blocks x 256
    const int gidx = blockIdx.x * blockDim.x + threadIdx.x;
    const int t   = gidx / (TM * TN / 4);        // remainder tile 0..31
    const int e4  = gidx % (TM * TN / 4);        // float4 index within tile
    const int e   = e4 * 4;

    const float* pb = g_part + (size_t)t * KSPLIT * (TM * TN) + e;
    float4 s = *reinterpret_cast<const float4*>(pb);
    #pragma unroll
    for (int p = 1; p < KSPLIT; p++) {
        float4 v = *reinterpret_cast<const float4*>(pb + (size_t)p * (TM * TN));
        s.x += v.x; s.y += v.y; s.z += v.z; s.w += v.w;
    }

    const int tile = MAIN_TILES + t;
    const int mt = tile % MT;
    const int nt = (tile / MT) % NT;
    const int b  = tile / (MT * NT);
    const int row = e / TN;          // 0..127
    const int col = e % TN;
    float* op = out + ((size_t)b * D_DIM + mt * TM + row) * N_DIM + nt * TN + col;
    *reinterpret_cast<float4*>(op) = s;
}

// ---------------- host launch ----------------
extern "C" void kernel_launch(void* const* d_in, const int* in_sizes, int n_in,
                              void* d_out, int out_size)
{
    const float* x;
    const float* adj;
    if (in_sizes[0] == B_DIM * D_DIM * N_DIM) {
        x = (const float*)d_in[0]; adj = (const float*)d_in[1];
    } else {
        x = (const float*)d_in[1]; adj = (const float*)d_in[0];
    }

    __half* xh;
    __half* adjh;
    cudaGetSymbolAddress((void**)&xh, g_xh);
    cudaGetSymbolAddress((void**)&adjh, g_adjh);

    const size_t nx = (size_t)B_DIM * D_DIM * N_DIM;
    const size_t na = (size_t)B_DIM * N_DIM * N_DIM;
    cvt_f2h_kernel<<<2048, 256>>>(x, xh, nx);
    cvt_f2h_kernel<<<4096, 256>>>(adj, adjh, na);

    cudaFuncSetAttribute(gcn_f16_mma_kernel, cudaFuncAttributeMaxDynamicSharedMemorySize, SMEM_BYTES);
    cudaFuncSetAttribute(gcn_f16_mma_rem_kernel, cudaFuncAttributeMaxDynamicSharedMemorySize, SMEM_BYTES);

    // remainder first: its single short wave overlaps the tail drain of nothing,
    // but keeping it before kernel1 lets its partial-writes complete while k1 fills the machine.
    gcn_f16_mma_rem_kernel<<<REM_TILES * KSPLIT, 128, SMEM_BYTES>>>();
    gcn_f16_mma_kernel<<<MAIN_TILES, 128, SMEM_BYTES>>>((float*)d_out);
    reduce_rem_kernel<<<(REM_TILES * TM * TN / 4) / 256, 256>>>((float*)d_out);
}